// round 7
// baseline (speedup 1.0000x reference)
#include <cuda_runtime.h>
#include <cuda_bf16.h>
#include <cstdint>

// RotationComponent: w_rotated = w @ rot, a_rotated = x @ rot, where rot is a
// normalized randomized Hadamard matrix: rot[i,j] = H[i,j] * rot[0,j], H the
// 4096x4096 Sylvester Hadamard (symmetric, H[0,:] = +1). Hence
//   (v @ rot)[j] = FWHT(v)[j] * rot[0,j]
// with per-column scales read from rot's first row (exact).
//
// One CTA per row. Shuffle-free FWHT (stages commute), phases:
//   P1: regs = i-bits {9..6}   i = (t>>6)*1024 + r*64 + (t&63)   (LDG coalesced)
//   P2: regs = i-bits {5..2}   i = J*64 + r*4 + e2, J = warp*8 + lane{4..2},
//                              e2 = lane{1..0}                    (smem only)
//   P3: regs = i-bits {11,10,1,0}  i = c*1024 + t*4 + e
//       -> 4 aligned float4: LDS.128 from smem, rot LDG.128, STG.128
// SMEM swizzle (16B-granular, 2 SASS ops): phys = i ^ ((i>>4) & 28); verified
// conflict-free for all four smem patterns, preserves 16B blocks for LDS.128.
//
// __launch_bounds__(256, 8): cap at 32 regs -> 8 CTAs/SM (full occupancy),
// raising resident MLP to cover the DRAM-latency gap seen at occ=68%.

#define DIM 4096
#define W_ROWS 4096
#define X_ROWS 8192   // 4 * 2048
#define THREADS 256

__device__ __forceinline__ int swz(int i)
{
    return i ^ ((i >> 4) & 28);
}

__global__ __launch_bounds__(THREADS, 8)
void fwht_rotate_kernel(const float* __restrict__ w,
                        const float* __restrict__ x,
                        const float* __restrict__ rot,
                        float* __restrict__ out)
{
    __shared__ float smem[DIM];

    const int row  = blockIdx.x;
    const int t    = threadIdx.x;
    const int lane = t & 31;
    const int warp = t >> 5;

    const float* src = (row < W_ROWS)
        ? (w + (size_t)row * DIM)
        : (x + (size_t)(row - W_ROWS) * DIM);

    float v[16];

    // ---- P1: i = (t>>6)*1024 + r*64 + (t&63); LDG coalesced (1 line/instr) --
    const int p1_base = (t >> 6) * 1024 + (t & 63);
    #pragma unroll
    for (int r = 0; r < 16; r++) {
        v[r] = src[p1_base + r * 64];
    }

    // ---- P1 butterflies: i-bits {9..6} (r bits 3..0) ----
    #pragma unroll
    for (int m = 8; m >= 1; m >>= 1) {
        #pragma unroll
        for (int r = 0; r < 16; r++) {
            if ((r & m) == 0) {
                float a = v[r], b = v[r | m];
                v[r]     = a + b;
                v[r | m] = a - b;
            }
        }
    }

    // ---- T1: swizzled smem write (banks = lane ^ const per instr, CF) ----
    #pragma unroll
    for (int r = 0; r < 16; r++) {
        smem[swz(p1_base + r * 64)] = v[r];
    }
    __syncthreads();

    // ---- P2: i = J*64 + r*4 + e2; J = warp*8 + lane{4..2}, e2 = lane{1..0} --
    const int p2_base = (warp * 8 + ((lane >> 2) & 7)) * 64 + (lane & 3);
    #pragma unroll
    for (int r = 0; r < 16; r++) {
        v[r] = smem[swz(p2_base + r * 4)];
    }

    // ---- P2 butterflies: i-bits {5..2} ----
    #pragma unroll
    for (int m = 8; m >= 1; m >>= 1) {
        #pragma unroll
        for (int r = 0; r < 16; r++) {
            if ((r & m) == 0) {
                float a = v[r], b = v[r | m];
                v[r]     = a + b;
                v[r | m] = a - b;
            }
        }
    }

    // ---- T2: write back to the same per-thread addresses (no hazard) ----
    #pragma unroll
    for (int r = 0; r < 16; r++) {
        smem[swz(p2_base + r * 4)] = v[r];
    }
    __syncthreads();

    // ---- P3: i = c*1024 + t*4 + e; LDS.128 (swizzle preserves 16B blocks) --
    const int p3_base = t * 4;
    #pragma unroll
    for (int c = 0; c < 4; c++) {
        float4 q = *(const float4*)(smem + swz(c * 1024 + p3_base));
        v[c * 4 + 0] = q.x;
        v[c * 4 + 1] = q.y;
        v[c * 4 + 2] = q.z;
        v[c * 4 + 3] = q.w;
    }

    // ---- P3 butterflies: bit11<->c1 (mask 8), bit10<->c0 (mask 4),
    //      bit1<->e1 (mask 2), bit0<->e0 (mask 1) ----
    #pragma unroll
    for (int m = 8; m >= 1; m >>= 1) {
        #pragma unroll
        for (int r = 0; r < 16; r++) {
            if ((r & m) == 0) {
                float a = v[r], b = v[r | m];
                v[r]     = a + b;
                v[r | m] = a - b;
            }
        }
    }

    // ---- Epilogue: 4 aligned float4 stores at i = c*1024 + t*4, scaled by
    //      rot[0, i] (LDG.128, L1-hit after first CTAs) ----
    float* dst = out + (size_t)row * DIM;
    #pragma unroll
    for (int c = 0; c < 4; c++) {
        const int idx = c * 1024 + p3_base;
        float4 s = __ldg((const float4*)(rot + idx));
        float4 o;
        o.x = v[c * 4 + 0] * s.x;
        o.y = v[c * 4 + 1] * s.y;
        o.z = v[c * 4 + 2] * s.z;
        o.w = v[c * 4 + 3] * s.w;
        *(float4*)(dst + idx) = o;
    }
}

extern "C" void kernel_launch(void* const* d_in, const int* in_sizes, int n_in,
                              void* d_out, int out_size)
{
    const float* w   = (const float*)d_in[0];   // [4096, 4096]
    const float* x   = (const float*)d_in[1];   // [4, 2048, 4096]
    const float* rot = (const float*)d_in[2];   // [4096, 4096]
    float* out = (float*)d_out;                 // w_rotated then a_rotated

    (void)in_sizes; (void)n_in; (void)out_size;

    fwht_rotate_kernel<<<W_ROWS + X_ROWS, THREADS>>>(w, x, rot, out);
}

// round 8
// speedup vs baseline: 1.0502x; 1.0502x over previous
#include <cuda_runtime.h>
#include <cuda_bf16.h>
#include <cstdint>

// RotationComponent: w_rotated = w @ rot, a_rotated = x @ rot, where rot is a
// normalized randomized Hadamard matrix: rot[i,j] = H[i,j] * rot[0,j], H the
// 4096x4096 Sylvester Hadamard (symmetric, H[0,:] = +1). Hence
//   (v @ rot)[j] = FWHT(v)[j] * rot[0,j]
// with per-column scales read from rot's first row (exact).
//
// One CTA per row. Input row arrives via ONE cp.async.bulk (TMA) 16KB copy
// into smem + mbarrier (no per-warp LDG burst -> no L1tex queue contention,
// the measured source of multi-CTA spread at MLP_p1=16). FWHT phases:
//   P1: regs = i-bits {9..6}   i = (t>>6)*1024 + r*64 + (t&63)  (LDS linear)
//   P2: regs = i-bits {5..2}   i = J*64 + r*4 + e2              (smem only)
//   P3: regs = i-bits {11,10,1,0}  i = c*1024 + t*4 + e
//       -> 4 aligned float4: LDS.128, rot LDG.128 (L1-hit), STG.128
// SMEM swizzle (16B-granular): phys = i ^ ((i>>4) & 28); conflict-free for
// all smem patterns, preserves 16B blocks for the P3 LDS.128.

#define DIM 4096
#define W_ROWS 4096
#define X_ROWS 8192   // 4 * 2048
#define THREADS 256
#define ROW_BYTES (DIM * 4)

__device__ __forceinline__ int swz(int i)
{
    return i ^ ((i >> 4) & 28);
}

__device__ __forceinline__ uint32_t smem_u32(const void* p)
{
    uint32_t a;
    asm("{ .reg .u64 t; cvta.to.shared.u64 t, %1; cvt.u32.u64 %0, t; }"
        : "=r"(a) : "l"(p));
    return a;
}

__global__ __launch_bounds__(THREADS)
void fwht_rotate_kernel(const float* __restrict__ w,
                        const float* __restrict__ x,
                        const float* __restrict__ rot,
                        float* __restrict__ out)
{
    __shared__ float buf[DIM];
    __shared__ __align__(8) unsigned long long mbar;

    const int row  = blockIdx.x;
    const int t    = threadIdx.x;
    const int lane = t & 31;
    const int warp = t >> 5;

    const float* src = (row < W_ROWS)
        ? (w + (size_t)row * DIM)
        : (x + (size_t)(row - W_ROWS) * DIM);

    const uint32_t mb = smem_u32(&mbar);

    // ---- TMA bulk load: one 16KB transfer, engine-driven ----
    if (t == 0) {
        asm volatile("mbarrier.init.shared.b64 [%0], 1;" :: "r"(mb) : "memory");
    }
    __syncthreads();
    if (t == 0) {
        asm volatile("mbarrier.arrive.expect_tx.shared.b64 _, [%0], %1;"
                     :: "r"(mb), "r"((uint32_t)ROW_BYTES) : "memory");
        asm volatile("cp.async.bulk.shared::cta.global.mbarrier::complete_tx::bytes "
                     "[%0], [%1], %2, [%3];"
                     :: "r"(smem_u32(buf)), "l"(src),
                        "r"((uint32_t)ROW_BYTES), "r"(mb)
                     : "memory");
    }
    {   // wait parity 0 (HW sleep, not poll)
        asm volatile(
            "{\n\t"
            ".reg .pred P1;\n\t"
            "WAIT_LOOP_%=:\n\t"
            "mbarrier.try_wait.parity.acquire.cta.shared::cta.b64 P1, [%0], 0, 0x989680;\n\t"
            "@P1 bra.uni WAIT_DONE_%=;\n\t"
            "bra.uni WAIT_LOOP_%=;\n\t"
            "WAIT_DONE_%=:\n\t"
            "}"
            :: "r"(mb) : "memory");
    }

    float v[16];

    // ---- P1: read linear from smem: i = (t>>6)*1024 + r*64 + (t&63) ----
    const int p1_base = (t >> 6) * 1024 + (t & 63);
    #pragma unroll
    for (int r = 0; r < 16; r++) {
        v[r] = buf[p1_base + r * 64];
    }

    // ---- P1 butterflies: i-bits {9..6} ----
    #pragma unroll
    for (int m = 8; m >= 1; m >>= 1) {
        #pragma unroll
        for (int r = 0; r < 16; r++) {
            if ((r & m) == 0) {
                float a = v[r], b = v[r | m];
                v[r]     = a + b;
                v[r | m] = a - b;
            }
        }
    }

    // ---- In-place buffer reuse: all P1 reads must complete first ----
    __syncthreads();

    // ---- T1: swizzled smem write (banks = lane ^ const per instr, CF) ----
    #pragma unroll
    for (int r = 0; r < 16; r++) {
        buf[swz(p1_base + r * 64)] = v[r];
    }
    __syncthreads();

    // ---- P2: i = J*64 + r*4 + e2; J = warp*8 + lane{4..2}, e2 = lane{1..0} --
    const int p2_base = (warp * 8 + ((lane >> 2) & 7)) * 64 + (lane & 3);
    #pragma unroll
    for (int r = 0; r < 16; r++) {
        v[r] = buf[swz(p2_base + r * 4)];
    }

    // ---- P2 butterflies: i-bits {5..2} ----
    #pragma unroll
    for (int m = 8; m >= 1; m >>= 1) {
        #pragma unroll
        for (int r = 0; r < 16; r++) {
            if ((r & m) == 0) {
                float a = v[r], b = v[r | m];
                v[r]     = a + b;
                v[r | m] = a - b;
            }
        }
    }

    // ---- T2: write back to the same per-thread addresses (no hazard) ----
    #pragma unroll
    for (int r = 0; r < 16; r++) {
        buf[swz(p2_base + r * 4)] = v[r];
    }
    __syncthreads();

    // ---- P3: i = c*1024 + t*4 + e; LDS.128 (swizzle preserves 16B blocks) --
    const int p3_base = t * 4;
    #pragma unroll
    for (int c = 0; c < 4; c++) {
        float4 q = *(const float4*)(buf + swz(c * 1024 + p3_base));
        v[c * 4 + 0] = q.x;
        v[c * 4 + 1] = q.y;
        v[c * 4 + 2] = q.z;
        v[c * 4 + 3] = q.w;
    }

    // ---- P3 butterflies: bit11<->c1 (8), bit10<->c0 (4), bit1<->e1 (2),
    //      bit0<->e0 (1) ----
    #pragma unroll
    for (int m = 8; m >= 1; m >>= 1) {
        #pragma unroll
        for (int r = 0; r < 16; r++) {
            if ((r & m) == 0) {
                float a = v[r], b = v[r | m];
                v[r]     = a + b;
                v[r | m] = a - b;
            }
        }
    }

    // ---- Epilogue: 4 aligned float4 stores at i = c*1024 + t*4, scaled by
    //      rot[0, i] (LDG.128, L1-hit after first CTAs) ----
    float* dst = out + (size_t)row * DIM;
    #pragma unroll
    for (int c = 0; c < 4; c++) {
        const int idx = c * 1024 + p3_base;
        float4 s = __ldg((const float4*)(rot + idx));
        float4 o;
        o.x = v[c * 4 + 0] * s.x;
        o.y = v[c * 4 + 1] * s.y;
        o.z = v[c * 4 + 2] * s.z;
        o.w = v[c * 4 + 3] * s.w;
        *(float4*)(dst + idx) = o;
    }
}

extern "C" void kernel_launch(void* const* d_in, const int* in_sizes, int n_in,
                              void* d_out, int out_size)
{
    const float* w   = (const float*)d_in[0];   // [4096, 4096]
    const float* x   = (const float*)d_in[1];   // [4, 2048, 4096]
    const float* rot = (const float*)d_in[2];   // [4096, 4096]
    float* out = (float*)d_out;                 // w_rotated then a_rotated

    (void)in_sizes; (void)n_in; (void)out_size;

    fwht_rotate_kernel<<<W_ROWS + X_ROWS, THREADS>>>(w, x, rot, out);
}